// round 2
// baseline (speedup 1.0000x reference)
#include <cuda_runtime.h>
#include <cstdint>
#include <cstddef>

#define N_NODES 100000
#define DIM 128
#define N_REL 2
#define N_EDGES 500000

// ---------------- scratch (no allocations allowed) ----------------
__device__ float g_h1[(size_t)N_NODES * DIM];   // layer1 output (pre-relu)
__device__ float g_h2[(size_t)N_NODES * DIM];   // layer2 output (pre-relu)
__device__ float g_xr0[(size_t)N_NODES * DIM];  // x @ W_rel[0]
__device__ float g_xr1[(size_t)N_NODES * DIM];  // x @ W_rel[1]
__device__ float g_cnt[(size_t)N_REL * N_NODES]; // counts -> 1/max(cnt,1)

// ---------------- helpers ----------------
__device__ __forceinline__ uint64_t bcast2(float x) {
    uint32_t xi = __float_as_uint(x);
    uint64_t r;
    asm("mov.b64 %0, {%1, %1};" : "=l"(r) : "r"(xi));
    return r;
}
__device__ __forceinline__ void fma2(uint64_t& d, uint64_t a, uint64_t b) {
    asm("fma.rn.f32x2 %0, %1, %2, %0;" : "+l"(d) : "l"(a), "l"(b));
}

// ---------------- degree count / inverse ----------------
__global__ void zero_cnt_k() {
    int i = blockIdx.x * blockDim.x + threadIdx.x;
    if (i < N_REL * N_NODES) g_cnt[i] = 0.0f;
}
__global__ void count_k(const int* __restrict__ ei,
                        const int* __restrict__ et) {
    int e = blockIdx.x * blockDim.x + threadIdx.x;
    if (e < N_EDGES) {
        int dst = ei[N_EDGES + e];
        int r = et[e];
        atomicAdd(&g_cnt[(size_t)r * N_NODES + dst], 1.0f);
    }
}
__global__ void inv_k() {
    int i = blockIdx.x * blockDim.x + threadIdx.x;
    if (i < N_REL * N_NODES) g_cnt[i] = 1.0f / fmaxf(g_cnt[i], 1.0f);
}

// ---------------- fused triple GEMM:  C{root,rel0,rel1} = act(A) @ W + (b) ----
// A: [M,128] fp32.  blockIdx.y selects which weight/output.
// 128x128 tile, BK=32, 256 threads, 8x8 microtile with f32x2 packed FMAs.
__global__ void __launch_bounds__(256, 2)
gemm3_k(const float* __restrict__ Aparam,
        const float* __restrict__ Wroot,
        const float* __restrict__ Wrel,
        const float* __restrict__ bias,
        int relu, int phase, int a_from_h1)
{
    const float* A = a_from_h1 ? g_h1 : Aparam;
    const float* W;
    float* C;
    if (blockIdx.y == 0)      { W = Wroot;           C = phase ? g_h2 : g_h1; }
    else if (blockIdx.y == 1) { W = Wrel;            C = g_xr0; }
    else                      { W = Wrel + DIM*DIM;  C = g_xr1; }

    __shared__ float As[32][132];   // transposed A tile: As[k][row]
    __shared__ float Ws[32][128];   // Ws[k][n]

    const int t  = threadIdx.x;
    const int tx = t & 15;   // column group  (8 cols)
    const int ty = t >> 4;   // row group     (8 rows)
    const int m0 = blockIdx.x * 128;

    uint64_t acc[4][8];
#pragma unroll
    for (int i = 0; i < 4; i++)
#pragma unroll
        for (int j = 0; j < 8; j++) acc[i][j] = 0ull;

    for (int kb = 0; kb < DIM; kb += 32) {
        // load A tile (transpose into smem)
#pragma unroll
        for (int i = 0; i < 4; i++) {
            int idx = t + i * 256;           // 0..1023
            int row = idx >> 3;              // 0..127
            int kq  = idx & 7;               // float4 index within 32 cols
            float4 v = make_float4(0.f, 0.f, 0.f, 0.f);
            int gr = m0 + row;
            if (gr < N_NODES)
                v = *(const float4*)(A + (size_t)gr * DIM + kb + kq * 4);
            if (relu) {
                v.x = fmaxf(v.x, 0.f); v.y = fmaxf(v.y, 0.f);
                v.z = fmaxf(v.z, 0.f); v.w = fmaxf(v.w, 0.f);
            }
            As[kq * 4 + 0][row] = v.x;
            As[kq * 4 + 1][row] = v.y;
            As[kq * 4 + 2][row] = v.z;
            As[kq * 4 + 3][row] = v.w;
        }
        // load W tile
#pragma unroll
        for (int i = 0; i < 4; i++) {
            int idx = t + i * 256;
            int kk = idx >> 5;               // 0..31
            int nq = idx & 31;
            *(float4*)&Ws[kk][nq * 4] =
                *(const float4*)(W + (size_t)(kb + kk) * DIM + nq * 4);
        }
        __syncthreads();

#pragma unroll
        for (int kk = 0; kk < 32; kk++) {
            union { float4 f; uint64_t u[2]; } aA, aB, wA, wB;
            aA.f = *(const float4*)&As[kk][ty * 8];
            aB.f = *(const float4*)&As[kk][ty * 8 + 4];
            wA.f = *(const float4*)&Ws[kk][tx * 8];
            wB.f = *(const float4*)&Ws[kk][tx * 8 + 4];
            uint64_t a2[4] = { aA.u[0], aA.u[1], aB.u[0], aB.u[1] };
            uint64_t wb[8];
            wb[0] = bcast2(wA.f.x); wb[1] = bcast2(wA.f.y);
            wb[2] = bcast2(wA.f.z); wb[3] = bcast2(wA.f.w);
            wb[4] = bcast2(wB.f.x); wb[5] = bcast2(wB.f.y);
            wb[6] = bcast2(wB.f.z); wb[7] = bcast2(wB.f.w);
#pragma unroll
            for (int i = 0; i < 4; i++)
#pragma unroll
                for (int j = 0; j < 8; j++)
                    fma2(acc[i][j], a2[i], wb[j]);
        }
        __syncthreads();
    }

    // epilogue: add bias (root block only), store
    float bj[8];
#pragma unroll
    for (int j = 0; j < 8; j++)
        bj[j] = (blockIdx.y == 0) ? bias[tx * 8 + j] : 0.f;

#pragma unroll
    for (int i = 0; i < 4; i++) {
        int r0 = m0 + ty * 8 + 2 * i;
        float lo[8], hi[8];
#pragma unroll
        for (int j = 0; j < 8; j++) {
            union { uint64_t u; float2 f; } c; c.u = acc[i][j];
            lo[j] = c.f.x + bj[j];
            hi[j] = c.f.y + bj[j];
        }
        if (r0 < N_NODES) {
            *(float4*)(C + (size_t)r0 * DIM + tx * 8)     = make_float4(lo[0], lo[1], lo[2], lo[3]);
            *(float4*)(C + (size_t)r0 * DIM + tx * 8 + 4) = make_float4(lo[4], lo[5], lo[6], lo[7]);
        }
        if (r0 + 1 < N_NODES) {
            *(float4*)(C + (size_t)(r0 + 1) * DIM + tx * 8)     = make_float4(hi[0], hi[1], hi[2], hi[3]);
            *(float4*)(C + (size_t)(r0 + 1) * DIM + tx * 8 + 4) = make_float4(hi[4], hi[5], hi[6], hi[7]);
        }
    }
}

// ---------------- edge scatter: out[dst] += xr_r[src] * inv_cnt[r][dst] -------
// one warp per edge, lane handles 4 consecutive floats, vector red.
__global__ void scatter_k(const int* __restrict__ ei,
                          const int* __restrict__ et,
                          int phase)
{
    int e = blockIdx.x * (blockDim.x >> 5) + (threadIdx.x >> 5);
    if (e >= N_EDGES) return;
    int lane = threadIdx.x & 31;

    int src = ei[e];
    int dst = ei[N_EDGES + e];
    int r   = et[e];
    float w = g_cnt[(size_t)r * N_NODES + dst];   // holds 1/max(cnt,1)

    const float* xr = r ? g_xr1 : g_xr0;
    float* out = phase ? g_h2 : g_h1;

    float4 v = *(const float4*)(xr + (size_t)src * DIM + lane * 4);
    float* p = out + (size_t)dst * DIM + lane * 4;
    asm volatile("red.global.add.v4.f32 [%0], {%1,%2,%3,%4};"
                 :: "l"(p), "f"(v.x * w), "f"(v.y * w), "f"(v.z * w), "f"(v.w * w)
                 : "memory");
}

// ---------------- classifier: out = relu(h2) @ Wc + bc ------------------------
__global__ void cls_k(const float* __restrict__ Wc,
                      const float* __restrict__ bc,
                      float* __restrict__ out)
{
    __shared__ float sW[DIM * 2];
    __shared__ float sb[2];
    if (threadIdx.x < DIM * 2) sW[threadIdx.x] = Wc[threadIdx.x];
    if (threadIdx.x < 2) sb[threadIdx.x] = bc[threadIdx.x];
    __syncthreads();

    int i = blockIdx.x * blockDim.x + threadIdx.x;
    if (i >= N_NODES) return;
    float a0 = sb[0], a1 = sb[1];
    const float4* hp = (const float4*)(g_h2 + (size_t)i * DIM);
#pragma unroll
    for (int k4 = 0; k4 < 32; k4++) {
        float4 h = hp[k4];
        h.x = fmaxf(h.x, 0.f); h.y = fmaxf(h.y, 0.f);
        h.z = fmaxf(h.z, 0.f); h.w = fmaxf(h.w, 0.f);
        int k = k4 * 4;
        a0 += h.x * sW[(k + 0) * 2 + 0]; a1 += h.x * sW[(k + 0) * 2 + 1];
        a0 += h.y * sW[(k + 1) * 2 + 0]; a1 += h.y * sW[(k + 1) * 2 + 1];
        a0 += h.z * sW[(k + 2) * 2 + 0]; a1 += h.z * sW[(k + 2) * 2 + 1];
        a0 += h.w * sW[(k + 3) * 2 + 0]; a1 += h.w * sW[(k + 3) * 2 + 1];
    }
    out[(size_t)i * 2 + 0] = a0;
    out[(size_t)i * 2 + 1] = a1;
}

// ---------------- launch -------------------------------------------------------
extern "C" void kernel_launch(void* const* d_in, const int* in_sizes, int n_in,
                              void* d_out, int out_size)
{
    const float* x          = (const float*)d_in[0];
    const int*   edge_index = (const int*)d_in[1];
    const int*   edge_type  = (const int*)d_in[2];
    const float* W_rel1     = (const float*)d_in[3];
    const float* W_root1    = (const float*)d_in[4];
    const float* b1         = (const float*)d_in[5];
    const float* W_rel2     = (const float*)d_in[6];
    const float* W_root2    = (const float*)d_in[7];
    const float* b2         = (const float*)d_in[8];
    const float* Wc         = (const float*)d_in[9];
    const float* bc         = (const float*)d_in[10];
    float* out = (float*)d_out;

    const int MB = (N_NODES + 127) / 128;        // 782

    // degree counts -> inverse (same for both layers)
    zero_cnt_k<<<(N_REL * N_NODES + 255) / 256, 256>>>();
    count_k<<<(N_EDGES + 255) / 256, 256>>>(edge_index, edge_type);
    inv_k<<<(N_REL * N_NODES + 255) / 256, 256>>>();

    // layer 1: h1 = x@W_root1+b1 ; xr0/xr1 = x@W_rel1[r] ; scatter into h1
    gemm3_k<<<dim3(MB, 3), 256>>>(x, W_root1, W_rel1, b1, /*relu=*/0, /*phase=*/0, /*a_from_h1=*/0);
    scatter_k<<<(N_EDGES + 7) / 8, 256>>>(edge_index, edge_type, /*phase=*/0);

    // layer 2: A = relu(h1)
    gemm3_k<<<dim3(MB, 3), 256>>>(nullptr, W_root2, W_rel2, b2, /*relu=*/1, /*phase=*/1, /*a_from_h1=*/1);
    scatter_k<<<(N_EDGES + 7) / 8, 256>>>(edge_index, edge_type, /*phase=*/1);

    // classifier
    cls_k<<<(N_NODES + 255) / 256, 256>>>(Wc, bc, out);
}

// round 4
// speedup vs baseline: 1.3866x; 1.3866x over previous
#include <cuda_runtime.h>
#include <cuda_bf16.h>
#include <cstdint>
#include <cstddef>

#define N_NODES 100000
#define DIM 128
#define N_REL 2
#define N_EDGES 500000
#define MTILES ((N_NODES + 127) / 128)
#define STR 136   // padded smem row stride (bf16 elems): 272B -> conflict-free ldmatrix

// ---------------- scratch (no allocations allowed) ----------------
__device__ float g_h1[(size_t)N_NODES * DIM];
__device__ float g_h2[(size_t)N_NODES * DIM];
__device__ float g_xr0[(size_t)N_NODES * DIM];
__device__ float g_xr1[(size_t)N_NODES * DIM];
__device__ float g_cnt[(size_t)N_REL * N_NODES];
// split + transposed weights: [6][n][k] bf16  (0=root1,1=rel1_0,2=rel1_1,3=root2,4=rel2_0,5=rel2_1)
__device__ __nv_bfloat16 g_whi[6 * DIM * DIM];
__device__ __nv_bfloat16 g_wlo[6 * DIM * DIM];

// ---------------- helpers ----------------
__device__ __forceinline__ uint32_t smem_u32(const void* p) {
    uint32_t a;
    asm("{ .reg .u64 t; cvta.to.shared.u64 t, %1; cvt.u32.u64 %0, t; }" : "=r"(a) : "l"(p));
    return a;
}
__device__ __forceinline__ void ldsm_x4(uint32_t* r, uint32_t addr) {
    asm volatile("ldmatrix.sync.aligned.m8n8.x4.shared.b16 {%0,%1,%2,%3}, [%4];"
                 : "=r"(r[0]), "=r"(r[1]), "=r"(r[2]), "=r"(r[3]) : "r"(addr));
}
__device__ __forceinline__ void mma16816(float* c, const uint32_t* a, uint32_t b0, uint32_t b1) {
    asm volatile("mma.sync.aligned.m16n8k16.row.col.f32.bf16.bf16.f32 "
                 "{%0,%1,%2,%3}, {%4,%5,%6,%7}, {%8,%9}, {%0,%1,%2,%3};"
                 : "+f"(c[0]), "+f"(c[1]), "+f"(c[2]), "+f"(c[3])
                 : "r"(a[0]), "r"(a[1]), "r"(a[2]), "r"(a[3]), "r"(b0), "r"(b1));
}

// ---------------- degree count / inverse ----------------
__global__ void zero_cnt_k() {
    int i = blockIdx.x * blockDim.x + threadIdx.x;
    if (i < N_REL * N_NODES) g_cnt[i] = 0.0f;
}
__global__ void count_k(const int* __restrict__ ei, const int* __restrict__ et) {
    int e = blockIdx.x * blockDim.x + threadIdx.x;
    if (e < N_EDGES) {
        int dst = ei[N_EDGES + e];
        int r = et[e];
        atomicAdd(&g_cnt[(size_t)r * N_NODES + dst], 1.0f);
    }
}
__global__ void inv_k() {
    int i = blockIdx.x * blockDim.x + threadIdx.x;
    if (i < N_REL * N_NODES) g_cnt[i] = 1.0f / fmaxf(g_cnt[i], 1.0f);
}

// ---------------- weight split + transpose:  g_w*[w][n][k] ----------------
__global__ void conv_w_k(const float* __restrict__ Wroot1, const float* __restrict__ Wrel1,
                         const float* __restrict__ Wroot2, const float* __restrict__ Wrel2) {
    int id = blockIdx.x * blockDim.x + threadIdx.x;
    if (id >= 6 * DIM * DIM) return;
    int w = id >> 14;
    int rem = id & 16383;
    int k = rem >> 7, n = rem & 127;
    float v;
    switch (w) {
        case 0: v = Wroot1[rem]; break;
        case 1: v = Wrel1[rem]; break;
        case 2: v = Wrel1[DIM * DIM + rem]; break;
        case 3: v = Wroot2[rem]; break;
        case 4: v = Wrel2[rem]; break;
        default: v = Wrel2[DIM * DIM + rem]; break;
    }
    __nv_bfloat16 hi = __float2bfloat16(v);
    __nv_bfloat16 lo = __float2bfloat16(v - __bfloat162float(hi));
    size_t dst = (size_t)w * DIM * DIM + (size_t)n * DIM + k;   // transposed [n][k]
    g_whi[dst] = hi;
    g_wlo[dst] = lo;
}

// ---------------- HMMA split-bf16 GEMM ----------------
// grid (MTILES, 3): blockIdx.y selects {root, rel0, rel1}.
// 256 thr = 8 warps; warp (wm = wid&3, wn = wid>>2) computes 32x64 of 128x128 C tile.
// dynamic smem: Ahi | Alo | Whi | Wlo, each 128*STR bf16.
#define TILE_B ((size_t)128 * STR)             // elems per tile
#define SMEM_BYTES (4 * 128 * STR * 2)

__global__ void __launch_bounds__(256, 1)
hmma3_k(const float* __restrict__ Aparam, const float* __restrict__ biasp, int layer)
{
    extern __shared__ __nv_bfloat16 sm[];
    const int tid = threadIdx.x;
    const int wid = tid >> 5;
    const int lane = tid & 31;
    const int wm = wid & 3;
    const int wn = wid >> 2;
    const int m0 = blockIdx.x * 128;

    __nv_bfloat16* sAhi = sm;
    __nv_bfloat16* sAlo = sm + TILE_B;
    __nv_bfloat16* sWhi = sm + 2 * TILE_B;
    __nv_bfloat16* sWlo = sm + 3 * TILE_B;

    // ---- load + split A (128x128 f32) ----
    const float* A = layer ? g_h1 : Aparam;
#pragma unroll
    for (int i = 0; i < 16; i++) {
        int idx = tid + i * 256;
        int m = idx >> 5, k0 = (idx & 31) * 4;
        int gm = m0 + m;
        float4 v = make_float4(0.f, 0.f, 0.f, 0.f);
        if (gm < N_NODES) v = *(const float4*)(A + (size_t)gm * DIM + k0);
        if (layer) {
            v.x = fmaxf(v.x, 0.f); v.y = fmaxf(v.y, 0.f);
            v.z = fmaxf(v.z, 0.f); v.w = fmaxf(v.w, 0.f);
        }
        __nv_bfloat16 h0 = __float2bfloat16(v.x), h1 = __float2bfloat16(v.y);
        __nv_bfloat16 h2 = __float2bfloat16(v.z), h3 = __float2bfloat16(v.w);
        __nv_bfloat16 l0 = __float2bfloat16(v.x - __bfloat162float(h0));
        __nv_bfloat16 l1 = __float2bfloat16(v.y - __bfloat162float(h1));
        __nv_bfloat16 l2 = __float2bfloat16(v.z - __bfloat162float(h2));
        __nv_bfloat16 l3 = __float2bfloat16(v.w - __bfloat162float(h3));
        uint2 hv, lv;
        hv.x = (uint32_t)__bfloat16_as_ushort(h0) | ((uint32_t)__bfloat16_as_ushort(h1) << 16);
        hv.y = (uint32_t)__bfloat16_as_ushort(h2) | ((uint32_t)__bfloat16_as_ushort(h3) << 16);
        lv.x = (uint32_t)__bfloat16_as_ushort(l0) | ((uint32_t)__bfloat16_as_ushort(l1) << 16);
        lv.y = (uint32_t)__bfloat16_as_ushort(l2) | ((uint32_t)__bfloat16_as_ushort(l3) << 16);
        *(uint2*)(sAhi + (size_t)m * STR + k0) = hv;   // STR*2=272B row, k0*2 mult of 8 -> 8B aligned
        *(uint2*)(sAlo + (size_t)m * STR + k0) = lv;
    }
    // ---- load W (already split, transposed [n][k]) ----
    {
        int wsel = layer * 3 + blockIdx.y;
        const uint2* ghi = (const uint2*)(g_whi + (size_t)wsel * DIM * DIM);
        const uint2* glo = (const uint2*)(g_wlo + (size_t)wsel * DIM * DIM);
#pragma unroll
        for (int i = 0; i < 16; i++) {
            int idx = tid + i * 256;
            int n = idx >> 5, k0 = (idx & 31) * 4;
            *(uint2*)(sWhi + (size_t)n * STR + k0) = ghi[idx];
            *(uint2*)(sWlo + (size_t)n * STR + k0) = glo[idx];
        }
    }
    __syncthreads();

    const uint32_t sbase = smem_u32(sm);
    const uint32_t aB0 = sbase;                       // Ahi
    const uint32_t aB1 = sbase + (uint32_t)TILE_B * 2;   // Alo
    const uint32_t wB0 = sbase + (uint32_t)TILE_B * 4;   // Whi
    const uint32_t wB1 = sbase + (uint32_t)TILE_B * 6;   // Wlo

    // per-lane ldmatrix offsets
    const int a_r = lane & 15;
    const int a_c = (lane >> 4) << 3;
    const int b_r = (lane & 7) + ((lane >> 4) << 3);
    const int b_c = ((lane >> 3) & 1) << 3;

    float acc[2][8][4] = {};

    const uint32_t aSel[3] = { aB0, aB0, aB1 };
    const uint32_t wSel[3] = { wB0, wB1, wB0 };

#pragma unroll
    for (int p = 0; p < 3; p++) {
        const uint32_t aB = aSel[p], wB = wSel[p];
#pragma unroll
        for (int ks = 0; ks < 8; ks++) {
            const int k0 = ks * 16;
            uint32_t a[2][4], b[4][4];
#pragma unroll
            for (int tm = 0; tm < 2; tm++) {
                int row = wm * 32 + tm * 16 + a_r;
                ldsm_x4(a[tm], aB + (uint32_t)(row * STR + k0 + a_c) * 2);
            }
#pragma unroll
            for (int nt = 0; nt < 4; nt++) {
                int row = wn * 64 + nt * 16 + b_r;
                ldsm_x4(b[nt], wB + (uint32_t)(row * STR + k0 + b_c) * 2);
            }
#pragma unroll
            for (int tm = 0; tm < 2; tm++)
#pragma unroll
                for (int nt = 0; nt < 4; nt++) {
                    mma16816(acc[tm][nt * 2 + 0], a[tm], b[nt][0], b[nt][1]);
                    mma16816(acc[tm][nt * 2 + 1], a[tm], b[nt][2], b[nt][3]);
                }
        }
    }

    // ---- epilogue ----
    float* C;
    if (blockIdx.y == 0)      C = layer ? g_h2 : g_h1;
    else if (blockIdx.y == 1) C = g_xr0;
    else                      C = g_xr1;

    const int row_in = lane >> 2;        // 0..7
    const int colp = (lane & 3) * 2;
#pragma unroll
    for (int tm = 0; tm < 2; tm++) {
#pragma unroll
        for (int j = 0; j < 8; j++) {
            int n = wn * 64 + j * 8 + colp;
            float bj0 = 0.f, bj1 = 0.f;
            if (blockIdx.y == 0) { bj0 = __ldg(biasp + n); bj1 = __ldg(biasp + n + 1); }
            int gm = m0 + wm * 32 + tm * 16 + row_in;
            if (gm < N_NODES)
                *(float2*)(C + (size_t)gm * DIM + n) =
                    make_float2(acc[tm][j][0] + bj0, acc[tm][j][1] + bj1);
            if (gm + 8 < N_NODES)
                *(float2*)(C + (size_t)(gm + 8) * DIM + n) =
                    make_float2(acc[tm][j][2] + bj0, acc[tm][j][3] + bj1);
        }
    }
}

// ---------------- edge scatter ----------------
__global__ void scatter_k(const int* __restrict__ ei, const int* __restrict__ et, int phase)
{
    int e = blockIdx.x * (blockDim.x >> 5) + (threadIdx.x >> 5);
    if (e >= N_EDGES) return;
    int lane = threadIdx.x & 31;

    int src = ei[e];
    int dst = ei[N_EDGES + e];
    int r   = et[e];
    float w = g_cnt[(size_t)r * N_NODES + dst];

    const float* xr = r ? g_xr1 : g_xr0;
    float* out = phase ? g_h2 : g_h1;

    float4 v = *(const float4*)(xr + (size_t)src * DIM + lane * 4);
    float* p = out + (size_t)dst * DIM + lane * 4;
    asm volatile("red.global.add.v4.f32 [%0], {%1,%2,%3,%4};"
                 :: "l"(p), "f"(v.x * w), "f"(v.y * w), "f"(v.z * w), "f"(v.w * w)
                 : "memory");
}

// ---------------- classifier ----------------
__global__ void cls_k(const float* __restrict__ Wc, const float* __restrict__ bc,
                      float* __restrict__ out)
{
    __shared__ float sW[DIM * 2];
    __shared__ float sb[2];
    if (threadIdx.x < DIM * 2) sW[threadIdx.x] = Wc[threadIdx.x];
    if (threadIdx.x < 2) sb[threadIdx.x] = bc[threadIdx.x];
    __syncthreads();

    int i = blockIdx.x * blockDim.x + threadIdx.x;
    if (i >= N_NODES) return;
    float a0 = sb[0], a1 = sb[1];
    const float4* hp = (const float4*)(g_h2 + (size_t)i * DIM);
#pragma unroll
    for (int k4 = 0; k4 < 32; k4++) {
        float4 h = hp[k4];
        h.x = fmaxf(h.x, 0.f); h.y = fmaxf(h.y, 0.f);
        h.z = fmaxf(h.z, 0.f); h.w = fmaxf(h.w, 0.f);
        int k = k4 * 4;
        a0 += h.x * sW[(k + 0) * 2 + 0]; a1 += h.x * sW[(k + 0) * 2 + 1];
        a0 += h.y * sW[(k + 1) * 2 + 0]; a1 += h.y * sW[(k + 1) * 2 + 1];
        a0 += h.z * sW[(k + 2) * 2 + 0]; a1 += h.z * sW[(k + 2) * 2 + 1];
        a0 += h.w * sW[(k + 3) * 2 + 0]; a1 += h.w * sW[(k + 3) * 2 + 1];
    }
    out[(size_t)i * 2 + 0] = a0;
    out[(size_t)i * 2 + 1] = a1;
}

// ---------------- launch ----------------
extern "C" void kernel_launch(void* const* d_in, const int* in_sizes, int n_in,
                              void* d_out, int out_size)
{
    const float* x          = (const float*)d_in[0];
    const int*   edge_index = (const int*)d_in[1];
    const int*   edge_type  = (const int*)d_in[2];
    const float* W_rel1     = (const float*)d_in[3];
    const float* W_root1    = (const float*)d_in[4];
    const float* b1         = (const float*)d_in[5];
    const float* W_rel2     = (const float*)d_in[6];
    const float* W_root2    = (const float*)d_in[7];
    const float* b2         = (const float*)d_in[8];
    const float* Wc         = (const float*)d_in[9];
    const float* bc         = (const float*)d_in[10];
    float* out = (float*)d_out;

    static int smem_set = 0;
    if (!smem_set) {
        cudaFuncSetAttribute(hmma3_k, cudaFuncAttributeMaxDynamicSharedMemorySize, SMEM_BYTES);
        smem_set = 1;
    }

    // degree counts -> inverse
    zero_cnt_k<<<(N_REL * N_NODES + 255) / 256, 256>>>();
    count_k<<<(N_EDGES + 255) / 256, 256>>>(edge_index, edge_type);
    inv_k<<<(N_REL * N_NODES + 255) / 256, 256>>>();

    // weight split/transpose
    conv_w_k<<<(6 * DIM * DIM + 255) / 256, 256>>>(W_root1, W_rel1, W_root2, W_rel2);

    // layer 1
    hmma3_k<<<dim3(MTILES, 3), 256, SMEM_BYTES>>>(x, b1, 0);
    scatter_k<<<(N_EDGES + 7) / 8, 256>>>(edge_index, edge_type, 0);

    // layer 2
    hmma3_k<<<dim3(MTILES, 3), 256, SMEM_BYTES>>>(nullptr, b2, 1);
    scatter_k<<<(N_EDGES + 7) / 8, 256>>>(edge_index, edge_type, 1);

    // classifier
    cls_k<<<(N_NODES + 255) / 256, 256>>>(Wc, bc, out);
}

// round 5
// speedup vs baseline: 1.5304x; 1.1037x over previous
#include <cuda_runtime.h>
#include <cuda_bf16.h>
#include <cstdint>
#include <cstddef>

#define N_NODES 100000
#define DIM 128
#define N_REL 2
#define N_EDGES 500000
#define NB2 (N_REL * N_NODES)
#define MTILES ((N_NODES + 127) / 128)
#define STR 136                      // padded smem row stride (bf16 elems)
#define TILE_B (128 * STR)           // elems per 128x128 tile
#define SMEM_BYTES (6 * TILE_B * 2)  // Ahi,Alo + 2x(Whi,Wlo)
#define SCAN_GRID ((NB2 + 1023) / 1024)

// ---------------- scratch ----------------
__device__ float g_hr[(size_t)N_NODES * DIM];    // root output of current layer
__device__ float g_h1[(size_t)N_NODES * DIM];    // layer1 result (post-agg, pre-relu)
__device__ float g_xr0[(size_t)N_NODES * DIM];
__device__ float g_xr1[(size_t)N_NODES * DIM];
__device__ int   g_cnti[NB2];
__device__ int   g_off[NB2];
__device__ int   g_cur[NB2];
__device__ float g_inv[NB2];
__device__ int   g_esrc[N_EDGES];
__device__ int   g_part[SCAN_GRID];
__device__ __nv_bfloat16 g_whi[6 * DIM * DIM];   // [w][n][k] transposed, split
__device__ __nv_bfloat16 g_wlo[6 * DIM * DIM];

// ---------------- helpers ----------------
__device__ __forceinline__ uint32_t smem_u32(const void* p) {
    uint32_t a;
    asm("{ .reg .u64 t; cvta.to.shared.u64 t, %1; cvt.u32.u64 %0, t; }" : "=r"(a) : "l"(p));
    return a;
}
__device__ __forceinline__ void ldsm_x4(uint32_t* r, uint32_t addr) {
    asm volatile("ldmatrix.sync.aligned.m8n8.x4.shared.b16 {%0,%1,%2,%3}, [%4];"
                 : "=r"(r[0]), "=r"(r[1]), "=r"(r[2]), "=r"(r[3]) : "r"(addr));
}
__device__ __forceinline__ void mma16816(float* c, const uint32_t* a, uint32_t b0, uint32_t b1) {
    asm volatile("mma.sync.aligned.m16n8k16.row.col.f32.bf16.bf16.f32 "
                 "{%0,%1,%2,%3}, {%4,%5,%6,%7}, {%8,%9}, {%0,%1,%2,%3};"
                 : "+f"(c[0]), "+f"(c[1]), "+f"(c[2]), "+f"(c[3])
                 : "r"(a[0]), "r"(a[1]), "r"(a[2]), "r"(a[3]), "r"(b0), "r"(b1));
}
__device__ __forceinline__ void cp8(uint32_t dst, const void* src) {
    asm volatile("cp.async.ca.shared.global [%0], [%1], 8;" :: "r"(dst), "l"(src));
}
#define CP_COMMIT() asm volatile("cp.async.commit_group;" ::: "memory")
#define CP_WAIT_ALL() asm volatile("cp.async.wait_group 0;" ::: "memory")

// ---------------- CSR build ----------------
__global__ void zero_cnt_k() {
    int i = blockIdx.x * blockDim.x + threadIdx.x;
    if (i < NB2) g_cnti[i] = 0;
}
__global__ void count_k(const int* __restrict__ ei, const int* __restrict__ et) {
    int e = blockIdx.x * blockDim.x + threadIdx.x;
    if (e < N_EDGES) {
        int dst = ei[N_EDGES + e];
        int r = et[e];
        atomicAdd(&g_cnti[r * N_NODES + dst], 1);
    }
}
__global__ void scan1_k() {
    __shared__ int sh[1024];
    int tid = threadIdx.x;
    int idx = blockIdx.x * 1024 + tid;
    int v = (idx < NB2) ? g_cnti[idx] : 0;
    sh[tid] = v;
    __syncthreads();
#pragma unroll
    for (int d = 1; d < 1024; d <<= 1) {
        int t = (tid >= d) ? sh[tid - d] : 0;
        __syncthreads();
        sh[tid] += t;
        __syncthreads();
    }
    if (idx < NB2) g_off[idx] = sh[tid] - v;
    if (tid == 1023) g_part[blockIdx.x] = sh[1023];
}
__global__ void scan2_k() {
    if (threadIdx.x == 0) {
        int s = 0;
        for (int i = 0; i < SCAN_GRID; i++) { int t = g_part[i]; g_part[i] = s; s += t; }
    }
}
__global__ void scan3_k() {
    int idx = blockIdx.x * blockDim.x + threadIdx.x;
    if (idx < NB2) {
        int o = g_off[idx] + g_part[idx >> 10];
        g_off[idx] = o;
        g_cur[idx] = o;
        g_inv[idx] = 1.0f / fmaxf((float)g_cnti[idx], 1.0f);
    }
}
__global__ void place_k(const int* __restrict__ ei, const int* __restrict__ et) {
    int e = blockIdx.x * blockDim.x + threadIdx.x;
    if (e < N_EDGES) {
        int src = ei[e];
        int dst = ei[N_EDGES + e];
        int r = et[e];
        int pos = atomicAdd(&g_cur[r * N_NODES + dst], 1);
        g_esrc[pos] = src;
    }
}

// ---------------- weight split + transpose ----------------
__global__ void conv_w_k(const float* __restrict__ Wroot1, const float* __restrict__ Wrel1,
                         const float* __restrict__ Wroot2, const float* __restrict__ Wrel2) {
    int id = blockIdx.x * blockDim.x + threadIdx.x;
    if (id >= 6 * DIM * DIM) return;
    int w = id >> 14;
    int rem = id & 16383;
    int k = rem >> 7, n = rem & 127;
    float v;
    switch (w) {
        case 0: v = Wroot1[rem]; break;
        case 1: v = Wrel1[rem]; break;
        case 2: v = Wrel1[DIM * DIM + rem]; break;
        case 3: v = Wroot2[rem]; break;
        case 4: v = Wrel2[rem]; break;
        default: v = Wrel2[DIM * DIM + rem]; break;
    }
    __nv_bfloat16 hi = __float2bfloat16(v);
    __nv_bfloat16 lo = __float2bfloat16(v - __bfloat162float(hi));
    size_t dst = (size_t)w * DIM * DIM + (size_t)n * DIM + k;
    g_whi[dst] = hi;
    g_wlo[dst] = lo;
}

// ---------------- fused HMMA GEMM: one CTA computes {root,rel0,rel1} ----------
__global__ void __launch_bounds__(256, 1)
hmma_fused_k(const float* __restrict__ Aparam, const float* __restrict__ biasp, int layer)
{
    extern __shared__ __nv_bfloat16 sm[];
    const int tid = threadIdx.x;
    const int wid = tid >> 5;
    const int lane = tid & 31;
    const int wm = wid & 3;
    const int wn = wid >> 2;
    const int m0 = blockIdx.x * 128;

    const uint32_t sb = smem_u32(sm);
    const uint32_t aHi = sb;
    const uint32_t aLo = sb + (uint32_t)TILE_B * 2;
    const uint32_t wB0 = sb + (uint32_t)TILE_B * 4;   // buf0: hi, lo at +TILE_B*2
    const uint32_t wB1 = sb + (uint32_t)TILE_B * 8;   // buf1

    const int wbase = layer * 3;

    // prefetch W(output 0) into buf0 (overlaps A conversion)
    {
        const uint2* ph = (const uint2*)(g_whi + (size_t)wbase * DIM * DIM);
        const uint2* pl = (const uint2*)(g_wlo + (size_t)wbase * DIM * DIM);
#pragma unroll
        for (int i = 0; i < 16; i++) {
            int idx = tid + i * 256;
            int n = idx >> 5, k0 = (idx & 31) * 4;
            uint32_t off = (uint32_t)(n * STR + k0) * 2;
            cp8(wB0 + off, ph + idx);
            cp8(wB0 + (uint32_t)TILE_B * 2 + off, pl + idx);
        }
        CP_COMMIT();
    }

    // ---- convert A (128x128 f32 -> bf16 hi/lo) ----
    const float* A = layer ? g_h1 : Aparam;
    __nv_bfloat16* sAhi = sm;
    __nv_bfloat16* sAlo = sm + TILE_B;
#pragma unroll
    for (int i = 0; i < 16; i++) {
        int idx = tid + i * 256;
        int m = idx >> 5, k0 = (idx & 31) * 4;
        int gm = m0 + m;
        float4 v = make_float4(0.f, 0.f, 0.f, 0.f);
        if (gm < N_NODES) v = *(const float4*)(A + (size_t)gm * DIM + k0);
        if (layer) {
            v.x = fmaxf(v.x, 0.f); v.y = fmaxf(v.y, 0.f);
            v.z = fmaxf(v.z, 0.f); v.w = fmaxf(v.w, 0.f);
        }
        __nv_bfloat16 h0 = __float2bfloat16(v.x), h1 = __float2bfloat16(v.y);
        __nv_bfloat16 h2 = __float2bfloat16(v.z), h3 = __float2bfloat16(v.w);
        __nv_bfloat16 l0 = __float2bfloat16(v.x - __bfloat162float(h0));
        __nv_bfloat16 l1 = __float2bfloat16(v.y - __bfloat162float(h1));
        __nv_bfloat16 l2 = __float2bfloat16(v.z - __bfloat162float(h2));
        __nv_bfloat16 l3 = __float2bfloat16(v.w - __bfloat162float(h3));
        uint2 hv, lv;
        hv.x = (uint32_t)__bfloat16_as_ushort(h0) | ((uint32_t)__bfloat16_as_ushort(h1) << 16);
        hv.y = (uint32_t)__bfloat16_as_ushort(h2) | ((uint32_t)__bfloat16_as_ushort(h3) << 16);
        lv.x = (uint32_t)__bfloat16_as_ushort(l0) | ((uint32_t)__bfloat16_as_ushort(l1) << 16);
        lv.y = (uint32_t)__bfloat16_as_ushort(l2) | ((uint32_t)__bfloat16_as_ushort(l3) << 16);
        *(uint2*)(sAhi + (size_t)m * STR + k0) = hv;
        *(uint2*)(sAlo + (size_t)m * STR + k0) = lv;
    }
    __syncthreads();   // A tiles visible

    // per-lane ldmatrix offsets
    const int a_r = lane & 15;
    const int a_c = (lane >> 4) << 3;
    const int b_r = (lane & 7) + ((lane >> 4) << 3);
    const int b_c = ((lane >> 3) & 1) << 3;
    const uint32_t aoff = (uint32_t)((wm * 32 + a_r) * STR + a_c) * 2;
    const uint32_t boff = (uint32_t)((wn * 64 + b_r) * STR + b_c) * 2;

    for (int o = 0; o < 3; o++) {
        CP_WAIT_ALL();
        __syncthreads();   // W(o) ready; all warps done with buf being refilled

        const uint32_t wcur = (o & 1) ? wB1 : wB0;

        if (o < 2) {
            int b = (o + 1) & 1;
            uint32_t wnxt = b ? wB1 : wB0;
            const uint2* ph = (const uint2*)(g_whi + (size_t)(wbase + o + 1) * DIM * DIM);
            const uint2* pl = (const uint2*)(g_wlo + (size_t)(wbase + o + 1) * DIM * DIM);
#pragma unroll
            for (int i = 0; i < 16; i++) {
                int idx = tid + i * 256;
                int n = idx >> 5, k0 = (idx & 31) * 4;
                uint32_t off = (uint32_t)(n * STR + k0) * 2;
                cp8(wnxt + off, ph + idx);
                cp8(wnxt + (uint32_t)TILE_B * 2 + off, pl + idx);
            }
            CP_COMMIT();
        }

        float acc[2][8][4] = {};
        uint32_t af[2][2][4], bf[2][4][4];

        // load frags for t=0
        {
            const uint32_t aB = aHi, wBp = wcur;
            ldsm_x4(af[0][0], aB + aoff);
            ldsm_x4(af[0][1], aB + aoff + (uint32_t)(16 * STR) * 2);
#pragma unroll
            for (int nt = 0; nt < 4; nt++)
                ldsm_x4(bf[0][nt], wBp + boff + (uint32_t)(nt * 16 * STR) * 2);
        }

#pragma unroll
        for (int t = 0; t < 24; t++) {
            const int cur = t & 1;
            if (t < 23) {
                const int tn = t + 1;
                const int p = tn >> 3;
                const uint32_t k2 = (uint32_t)(tn & 7) * 32;
                const uint32_t aB = (p == 2) ? aLo : aHi;
                const uint32_t wBp = wcur + ((p == 1) ? (uint32_t)TILE_B * 2 : 0u);
                ldsm_x4(af[cur ^ 1][0], aB + aoff + k2);
                ldsm_x4(af[cur ^ 1][1], aB + aoff + (uint32_t)(16 * STR) * 2 + k2);
#pragma unroll
                for (int nt = 0; nt < 4; nt++)
                    ldsm_x4(bf[cur ^ 1][nt], wBp + boff + (uint32_t)(nt * 16 * STR) * 2 + k2);
            }
#pragma unroll
            for (int tm = 0; tm < 2; tm++)
#pragma unroll
                for (int nt = 0; nt < 4; nt++) {
                    mma16816(acc[tm][nt * 2 + 0], af[cur][tm], bf[cur][nt][0], bf[cur][nt][1]);
                    mma16816(acc[tm][nt * 2 + 1], af[cur][tm], bf[cur][nt][2], bf[cur][nt][3]);
                }
        }

        // epilogue
        float* C = (o == 0) ? g_hr : (o == 1 ? g_xr0 : g_xr1);
        const int row_in = lane >> 2;
        const int colp = (lane & 3) * 2;
#pragma unroll
        for (int tm = 0; tm < 2; tm++) {
#pragma unroll
            for (int j = 0; j < 8; j++) {
                int n = wn * 64 + j * 8 + colp;
                float bj0 = 0.f, bj1 = 0.f;
                if (o == 0) { bj0 = __ldg(biasp + n); bj1 = __ldg(biasp + n + 1); }
                int gm = m0 + wm * 32 + tm * 16 + row_in;
                if (gm < N_NODES)
                    *(float2*)(C + (size_t)gm * DIM + n) =
                        make_float2(acc[tm][j][0] + bj0, acc[tm][j][1] + bj1);
                if (gm + 8 < N_NODES)
                    *(float2*)(C + (size_t)(gm + 8) * DIM + n) =
                        make_float2(acc[tm][j][2] + bj0, acc[tm][j][3] + bj1);
            }
        }
    }
}

// ---------------- CSR aggregation (one warp per node) ----------------
// layer 0: h1[i] = hr[i] + sum_r inv*sum(xr_r[src]);  layer 1: logits directly.
__global__ void __launch_bounds__(256)
agg_k(const float* __restrict__ Wc, const float* __restrict__ bc,
      float* __restrict__ out, int layer)
{
    int gw = (blockIdx.x * blockDim.x + threadIdx.x) >> 5;
    if (gw >= N_NODES) return;
    int lane = threadIdx.x & 31;

    float4 acc = *(const float4*)(g_hr + (size_t)gw * DIM + lane * 4);

#pragma unroll
    for (int r = 0; r < 2; r++) {
        int idx = r * N_NODES + gw;
        int n = g_cnti[idx];
        if (n) {
            int s = g_off[idx];
            const float* xr = r ? g_xr1 : g_xr0;
            float4 s4 = make_float4(0.f, 0.f, 0.f, 0.f);
            int j = 0;
            for (; j + 2 <= n; j += 2) {
                int s0 = g_esrc[s + j], s1 = g_esrc[s + j + 1];
                float4 a = *(const float4*)(xr + (size_t)s0 * DIM + lane * 4);
                float4 b = *(const float4*)(xr + (size_t)s1 * DIM + lane * 4);
                s4.x += a.x + b.x; s4.y += a.y + b.y;
                s4.z += a.z + b.z; s4.w += a.w + b.w;
            }
            if (j < n) {
                int s0 = g_esrc[s + j];
                float4 a = *(const float4*)(xr + (size_t)s0 * DIM + lane * 4);
                s4.x += a.x; s4.y += a.y; s4.z += a.z; s4.w += a.w;
            }
            float w = g_inv[idx];
            acc.x += s4.x * w; acc.y += s4.y * w;
            acc.z += s4.z * w; acc.w += s4.w * w;
        }
    }

    if (layer == 0) {
        *(float4*)(g_h1 + (size_t)gw * DIM + lane * 4) = acc;
    } else {
        float h0 = fmaxf(acc.x, 0.f), h1 = fmaxf(acc.y, 0.f);
        float h2 = fmaxf(acc.z, 0.f), h3 = fmaxf(acc.w, 0.f);
        int k = lane * 4;
        float p0 = h0 * __ldg(Wc + (k + 0) * 2) + h1 * __ldg(Wc + (k + 1) * 2)
                 + h2 * __ldg(Wc + (k + 2) * 2) + h3 * __ldg(Wc + (k + 3) * 2);
        float p1 = h0 * __ldg(Wc + (k + 0) * 2 + 1) + h1 * __ldg(Wc + (k + 1) * 2 + 1)
                 + h2 * __ldg(Wc + (k + 2) * 2 + 1) + h3 * __ldg(Wc + (k + 3) * 2 + 1);
#pragma unroll
        for (int d = 16; d > 0; d >>= 1) {
            p0 += __shfl_down_sync(0xffffffffu, p0, d);
            p1 += __shfl_down_sync(0xffffffffu, p1, d);
        }
        if (lane == 0) {
            out[(size_t)gw * 2 + 0] = p0 + __ldg(bc);
            out[(size_t)gw * 2 + 1] = p1 + __ldg(bc + 1);
        }
    }
}

// ---------------- launch ----------------
extern "C" void kernel_launch(void* const* d_in, const int* in_sizes, int n_in,
                              void* d_out, int out_size)
{
    const float* x          = (const float*)d_in[0];
    const int*   edge_index = (const int*)d_in[1];
    const int*   edge_type  = (const int*)d_in[2];
    const float* W_rel1     = (const float*)d_in[3];
    const float* W_root1    = (const float*)d_in[4];
    const float* b1         = (const float*)d_in[5];
    const float* W_rel2     = (const float*)d_in[6];
    const float* W_root2    = (const float*)d_in[7];
    const float* b2         = (const float*)d_in[8];
    const float* Wc         = (const float*)d_in[9];
    const float* bc         = (const float*)d_in[10];
    float* out = (float*)d_out;

    cudaFuncSetAttribute(hmma_fused_k, cudaFuncAttributeMaxDynamicSharedMemorySize, SMEM_BYTES);

    // CSR build
    zero_cnt_k<<<(NB2 + 255) / 256, 256>>>();
    count_k<<<(N_EDGES + 255) / 256, 256>>>(edge_index, edge_type);
    scan1_k<<<SCAN_GRID, 1024>>>();
    scan2_k<<<1, 32>>>();
    scan3_k<<<(NB2 + 255) / 256, 256>>>();
    place_k<<<(N_EDGES + 255) / 256, 256>>>(edge_index, edge_type);

    // weight split/transpose
    conv_w_k<<<(6 * DIM * DIM + 255) / 256, 256>>>(W_root1, W_rel1, W_root2, W_rel2);

    // layer 1
    hmma_fused_k<<<MTILES, 256, SMEM_BYTES>>>(x, b1, 0);
    agg_k<<<(N_NODES * 32 + 255) / 256, 256>>>(Wc, bc, nullptr, 0);

    // layer 2 (+ fused classifier)
    hmma_fused_k<<<MTILES, 256, SMEM_BYTES>>>(nullptr, b2, 1);
    agg_k<<<(N_NODES * 32 + 255) / 256, 256>>>(Wc, bc, out, 1);
}